// round 11
// baseline (speedup 1.0000x reference)
#include <cuda_runtime.h>
#include <cuda_bf16.h>

// RNN: B=8192, T=2048, I=2, H=20
//   h_{t+1} = tanh(x_t @ W_ih^T + b_ih + b_hh + h_t @ W_hh^T)
//   out = h_T @ fc_w^T + fc_b ; h_state = h_T
//
// R11: ZERO-smem register-exchange design.
// 5 lanes per row (6 rows/warp, lanes 30-31 idle), 4 hidden units per lane,
// W_hh slice (4x20) packed in 40 u64 registers. h state lives ONLY in
// registers: each lane owns 2 packed f32x2 pairs (its 4 units). Per step the
// 10 pairs are broadcast group-wide via 20 SHFL.IDX -- shfl IS the sync:
// no STS, no LDS, no __syncwarp, no divergent branch anywhere in the loop.
// Chain/step: tanh -> pack -> shfl(26) -> 11-deep fma2 -> combine (~125 cyc
// vs ~550 effective for the smem round-trip designs R3/R5/R8).
// Each lane loads its own row's x (5 lanes same 16B sector -> coalesced).

#define BB 8192
#define TT 2048
#define HH 20
#define LPR 5          // lanes per row
#define RPW 6          // rows per warp (lanes 0..29)
#define UPL 4          // units per lane

typedef unsigned long long u64;

__device__ __forceinline__ u64 pack2(float lo, float hi) {
    u64 r; asm("mov.b64 %0, {%1, %2};" : "=l"(r) : "f"(lo), "f"(hi)); return r;
}
__device__ __forceinline__ float2 unpack2(u64 v) {
    float2 f; asm("mov.b64 {%0, %1}, %2;" : "=f"(f.x), "=f"(f.y) : "l"(v)); return f;
}
__device__ __forceinline__ u64 fma2(u64 a, u64 b, u64 c) {
    u64 d;
    asm("fma.rn.f32x2 %0, %1, %2, %3;" : "=l"(d) : "l"(a), "l"(b), "l"(c));
    return d;
}
__device__ __forceinline__ float tanh_fast(float a) {
    // tanh(a) = 1 - 2/(e+1), e = 2^(2a*log2e). |a| <= ~8 -> no clamp needed.
    float e, r;
    asm("ex2.approx.f32 %0, %1;" : "=f"(e) : "f"(a * 2.8853900817779268f));
    asm("rcp.approx.f32 %0, %1;" : "=f"(r) : "f"(e + 1.0f));
    return fmaf(-2.0f, r, 1.0f);
}

__global__ __launch_bounds__(32)
void rnn_fused_kernel(const float* __restrict__ x,
                      const float* __restrict__ Wih,
                      const float* __restrict__ Whh,
                      const float* __restrict__ bih,
                      const float* __restrict__ bhh,
                      const float* __restrict__ fcw,
                      const float* __restrict__ fcb,
                      float* __restrict__ out) {
    const int lane = (int)(threadIdx.x & 31u);
    int grp  = lane / LPR;                 // 0..5 active, 6 for lanes 30,31
    const bool act = (grp < RPW);
    if (!act) grp = RPW - 1;               // clamp idle lanes onto group 5
    const int part = lane - grp * LPR;     // 0..4 (lanes 30,31 -> 5,6 clamped)
    const int pc   = (part < LPR) ? part : (LPR - 1);
    const unsigned gbase = (unsigned)(grp * LPR);
    const unsigned FULL  = 0xFFFFFFFFu;

    const int row  = blockIdx.x * RPW + grp;
    const bool vrow = act && (row < BB) && (part < LPR);
    const int row_c = (row < BB) ? row : (BB - 1);

    // ---- per-lane constants: units j = 4*pc + u, k packed in pairs ----
    u64 W2[UPL][HH / 2];    // 40 u64 = 80 regs
    u64 w01[UPL], bias2[UPL];
#pragma unroll
    for (int u = 0; u < UPL; ++u) {
        const int j = pc * UPL + u;
        bias2[u] = pack2(bih[j] + bhh[j], 0.0f);
        w01[u]   = pack2(Wih[2 * j], Wih[2 * j + 1]);
#pragma unroll
        for (int p = 0; p < HH / 2; ++p)
            W2[u][p] = pack2(Whh[j * HH + 2 * p], Whh[j * HH + 2 * p + 1]);
    }

    // h state: my 2 pairs (units 4pc..4pc+3), start at 0
    u64 pA = 0ull, pB = 0ull;
    float h[UPL];
#pragma unroll
    for (int u = 0; u < UPL; ++u) h[u] = 0.0f;

    // x: [B, T, 2]; one u64 per t; ulonglong2 per 2 t. Each lane loads its
    // own row (group lanes hit the same sectors). 4 steps per chunk.
    const ulonglong2* xr2 =
        reinterpret_cast<const ulonglong2*>(x) + (size_t)row_c * (TT / 2);
    ulonglong2 xa = xr2[0];
    ulonglong2 xbv = xr2[1];
    const int NC = TT / 4;   // 512 chunks

    for (int c = 0; c < NC; ++c) {
        const int cn = (c + 1 < NC) ? (c + 1) : 0;   // branch-free prefetch
        const ulonglong2 xna = xr2[2 * cn];
        const ulonglong2 xnb = xr2[2 * cn + 1];
        u64 xs[4] = { xa.x, xa.y, xbv.x, xbv.y };

#pragma unroll
        for (int s = 0; s < 4; ++s) {
            // broadcast all 10 h-pairs within the 5-lane group (shfl = sync)
            u64 hp[HH / 2];
#pragma unroll
            for (int p = 0; p < HH / 2; ++p) {
                const u64 src = (p & 1) ? pB : pA;
                hp[p] = __shfl_sync(FULL, src, gbase + (unsigned)(p >> 1));
            }

            // 4 independent k=20 contractions (chains interleave for issue)
            u64 acc[UPL];
#pragma unroll
            for (int u = 0; u < UPL; ++u)
                acc[u] = fma2(xs[s], w01[u], bias2[u]);
#pragma unroll
            for (int p = 0; p < HH / 2; ++p)
#pragma unroll
                for (int u = 0; u < UPL; ++u)
                    acc[u] = fma2(hp[p], W2[u][p], acc[u]);

#pragma unroll
            for (int u = 0; u < UPL; ++u) {
                const float2 f = unpack2(acc[u]);
                h[u] = tanh_fast(f.x + f.y);
            }
            pA = pack2(h[0], h[1]);
            pB = pack2(h[2], h[3]);
        }
        xa = xna;
        xbv = xnb;
    }

    // ---- epilogue ----
    // h_state [1, B, H] right after out [B, 1]; 16B-aligned STG.128
    if (vrow) {
        float4* hs4 = reinterpret_cast<float4*>(out + BB + (size_t)row * HH + pc * UPL);
        *hs4 = make_float4(h[0], h[1], h[2], h[3]);
    }

    // fc head: per-lane partial, gather to part 0 of each group (uniform shfls)
    float ps = 0.0f;
#pragma unroll
    for (int u = 0; u < UPL; ++u)
        ps = fmaf(h[u], fcw[pc * UPL + u], ps);
    float tot = 0.0f;
#pragma unroll
    for (int j = 0; j < LPR; ++j)
        tot += __shfl_sync(FULL, ps, gbase + (unsigned)j);
    if (vrow && pc == 0 && part == 0)
        out[row] = tot + fcb[0];
}

extern "C" void kernel_launch(void* const* d_in, const int* in_sizes, int n_in,
                              void* d_out, int out_size) {
    const float* x   = (const float*)d_in[0];
    const float* Wih = (const float*)d_in[1];
    const float* Whh = (const float*)d_in[2];
    const float* bih = (const float*)d_in[3];
    const float* bhh = (const float*)d_in[4];
    const float* fcw = (const float*)d_in[5];
    const float* fcb = (const float*)d_in[6];
    float* out = (float*)d_out;

    const int nblocks = (BB + RPW - 1) / RPW;   // 1366 single-warp CTAs
    rnn_fused_kernel<<<nblocks, 32>>>(x, Wih, Whh, bih, bhh, fcw, fcb, out);
}

// round 12
// speedup vs baseline: 1.2693x; 1.2693x over previous
#include <cuda_runtime.h>
#include <cuda_bf16.h>

// RNN: B=8192, T=2048, I=2, H=20
//   h_{t+1} = tanh(x_t @ W_ih^T + b_ih + b_hh + h_t @ W_hh^T)
//   out = h_T @ fc_w^T + fc_b ; h_state = h_T
//
// R12: 5 lanes/row x 4 units/lane, 6 rows/warp (lanes 30-31 idle-clamped).
// Exchange medium: warp-local smem (shfl broadcast is rt~8/SMSP => 20-float
// broadcast via shfl is throughput-infeasible; 5x LDS.128 delivers 80B in 5
// MIO ops). Per lane-step: 5 LDS.128 + 44 fma2 (4 indep depth-11 chains) +
// 4 tanh + 1 STS.128 + 2 SHFL (x broadcast) + syncwarp ~= 78 instr.
// Per-SMSP-step: fma2 pipe 202 cyc (floor), issue ~180, MUFU 147, MIO ~140.
// 1366 single-warp CTAs = 2.31 warps/SMSP, 9.2 CTA/SM (1.08 balance).

#define BB 8192
#define TT 2048
#define HH 20
#define LPR 5          // lanes per row
#define RPW 6          // rows per warp (lanes 0..29 active)
#define UPL 4          // units per lane

typedef unsigned long long u64;

__device__ __forceinline__ u64 pack2(float lo, float hi) {
    u64 r; asm("mov.b64 %0, {%1, %2};" : "=l"(r) : "f"(lo), "f"(hi)); return r;
}
__device__ __forceinline__ float2 unpack2(u64 v) {
    float2 f; asm("mov.b64 {%0, %1}, %2;" : "=f"(f.x), "=f"(f.y) : "l"(v)); return f;
}
__device__ __forceinline__ u64 fma2(u64 a, u64 b, u64 c) {
    u64 d;
    asm("fma.rn.f32x2 %0, %1, %2, %3;" : "=l"(d) : "l"(a), "l"(b), "l"(c));
    return d;
}
__device__ __forceinline__ float tanh_fast(float a) {
    // tanh(a) = 1 - 2/(e+1), e = 2^(2a*log2e). |a| <= ~8 -> no clamp needed.
    float e, r;
    asm("ex2.approx.f32 %0, %1;" : "=f"(e) : "f"(a * 2.8853900817779268f));
    asm("rcp.approx.f32 %0, %1;" : "=f"(r) : "f"(e + 1.0f));
    return fmaf(-2.0f, r, 1.0f);
}

__global__ __launch_bounds__(32)
void rnn_fused_kernel(const float* __restrict__ x,
                      const float* __restrict__ Wih,
                      const float* __restrict__ Whh,
                      const float* __restrict__ bih,
                      const float* __restrict__ bhh,
                      const float* __restrict__ fcw,
                      const float* __restrict__ fcb,
                      float* __restrict__ out) {
    // [2 buffers][6 rows][20 floats]; row stride 80B (16-aligned for LDS/STS.128)
    __shared__ __align__(16) float hbuf[2][RPW][HH];

    const int lane = (int)(threadIdx.x & 31u);
    const bool act = (lane < RPW * LPR);            // lanes 30,31 idle
    int grp = lane / LPR;                            // 0..5 (6 for idle)
    if (!act) grp = RPW - 1;                         // clamp onto group 5
    const int ig0 = lane - grp * LPR;                // 0..4 (idle: 5,6)
    const int ig  = (ig0 < LPR) ? ig0 : (LPR - 1);   // clamped
    const unsigned gbase = (unsigned)(grp * LPR);
    const unsigned FULL  = 0xFFFFFFFFu;

    const int row  = blockIdx.x * RPW + grp;
    const bool vrow = act && (row < BB);
    const int row_c = (row < BB) ? row : (BB - 1);

    // ---- per-lane constants: units j = 4*ig + u, k packed in pairs ----
    u64 W2[UPL][HH / 2];      // 40 u64 = 80 regs
    u64 w01[UPL], bias2[UPL];
#pragma unroll
    for (int u = 0; u < UPL; ++u) {
        const int j = ig * UPL + u;
        bias2[u] = pack2(bih[j] + bhh[j], 0.0f);
        w01[u]   = pack2(Wih[2 * j], Wih[2 * j + 1]);
#pragma unroll
        for (int p = 0; p < HH / 2; ++p)
            W2[u][p] = pack2(Whh[j * HH + 2 * p], Whh[j * HH + 2 * p + 1]);
    }

    // h0 = 0 in buffer 0
    if (act) {
        float4* hz = reinterpret_cast<float4*>(&hbuf[0][grp][ig * UPL]);
        *hz = make_float4(0.0f, 0.0f, 0.0f, 0.0f);
    }
    __syncwarp();

    // x: [B, T, 2] as one u64 per (row, t). Lanes ig<4 hold steps 4c+ig.
    const u64* xr = reinterpret_cast<const u64*>(x) + (size_t)row_c * TT;
    const int igx = (ig < 4) ? ig : 3;
    u64 xb = xr[igx];
    const int NC = TT / 4;     // 512 chunks of 4 steps

    float h[UPL];
#pragma unroll
    for (int u = 0; u < UPL; ++u) h[u] = 0.0f;

    for (int c = 0; c < NC; ++c) {
        // branch-free prefetch (last iter re-reads chunk 0: in-bounds, unused)
        const int cn = (c + 1 < NC) ? (c + 1) : 0;
        const u64 xn = xr[cn * 4 + igx];

#pragma unroll
        for (int s = 0; s < 4; ++s) {
            const int rb = s & 1;    // t = 4c+s, parity = s&1 (4c even)
            const u64 xp = __shfl_sync(FULL, xb, gbase + (unsigned)s);

            // full previous h as 10 packed pairs: 5 broadcast LDS.128
            u64 hp[HH / 2];
            const ulonglong2* hq =
                reinterpret_cast<const ulonglong2*>(hbuf[rb][grp]);
#pragma unroll
            for (int q = 0; q < 5; ++q) {
                const ulonglong2 v = hq[q];
                hp[2 * q]     = v.x;
                hp[2 * q + 1] = v.y;
            }

            // 4 independent k=20 contractions (depth 11 each)
            u64 acc[UPL];
#pragma unroll
            for (int u = 0; u < UPL; ++u)
                acc[u] = fma2(xp, w01[u], bias2[u]);
#pragma unroll
            for (int p = 0; p < HH / 2; ++p)
#pragma unroll
                for (int u = 0; u < UPL; ++u)
                    acc[u] = fma2(hp[p], W2[u][p], acc[u]);

#pragma unroll
            for (int u = 0; u < UPL; ++u) {
                const float2 f = unpack2(acc[u]);
                h[u] = tanh_fast(f.x + f.y);
            }

            // one STS.128 publishes all 4 units
            if (act) {
                float4* hw = reinterpret_cast<float4*>(&hbuf[rb ^ 1][grp][ig * UPL]);
                *hw = make_float4(h[0], h[1], h[2], h[3]);
            }
            __syncwarp();
        }
        xb = xn;
    }

    // ---- epilogue ----
    // h_state [1, B, H] right after out [B, 1]; (row*20 + 4*ig)*4B is 16-aligned
    if (vrow) {
        float4* hs4 =
            reinterpret_cast<float4*>(out + BB + (size_t)row * HH + ig * UPL);
        *hs4 = make_float4(h[0], h[1], h[2], h[3]);
    }

    // fc head: per-lane partial over my 4 units, gather within 5-lane group
    float ps = 0.0f;
#pragma unroll
    for (int u = 0; u < UPL; ++u)
        ps = fmaf(h[u], fcw[ig * UPL + u], ps);
    float tot = 0.0f;
#pragma unroll
    for (int j = 0; j < LPR; ++j)
        tot += __shfl_sync(FULL, ps, gbase + (unsigned)j);
    if (vrow && ig0 == 0)
        out[row] = tot + fcb[0];
}

extern "C" void kernel_launch(void* const* d_in, const int* in_sizes, int n_in,
                              void* d_out, int out_size) {
    const float* x   = (const float*)d_in[0];
    const float* Wih = (const float*)d_in[1];
    const float* Whh = (const float*)d_in[2];
    const float* bih = (const float*)d_in[3];
    const float* bhh = (const float*)d_in[4];
    const float* fcw = (const float*)d_in[5];
    const float* fcb = (const float*)d_in[6];
    float* out = (float*)d_out;

    const int nblocks = (BB + RPW - 1) / RPW;   // 1366 single-warp CTAs
    rnn_fused_kernel<<<nblocks, 32>>>(x, Wih, Whh, bih, bhh, fcw, fcb, out);
}

// round 14
// speedup vs baseline: 1.5168x; 1.1950x over previous
#include <cuda_runtime.h>
#include <cuda_bf16.h>

// RNN: B=8192, T=2048, I=2, H=20
//   h_{t+1} = tanh(x_t @ W_ih^T + b_ih + b_hh + h_t @ W_hh^T)
//   out = h_T @ fc_w^T + fc_b ; h_state = h_T
//
// R13: R3's topology (4 lanes/row, 5 units/lane, 8 rows/warp, 1024 warps --
// the proven 68%-issue-efficiency shfl-exchange regime) with ~30% fewer
// issue slots:
//  * k-permutation: contraction is order-free, so k's are paired WITHIN each
//    producer lane -> 8 clean u64 pairs + 4 scalar leftovers per step.
//    MAC = 45 fma2 + 20 FFMA (vs R3's 110 FFMA), zero consumer-side packs.
//  * exchange = 15 SHFL (3 source lanes x (2 u64 + 1 scalar)); own h read
//    from registers; W rotated per-lane at init so no runtime indexing.
//  * W,b pre-scaled by 2*log2e -> tanh = ex2+add+rcp+fma (no FMUL).
//  * x loaded per-lane from own row (no x-shfl).

#define BB 8192
#define TT 2048
#define HH 20
#define LPR 4     // lanes per row
#define UPL 5     // units per lane
#define RPW 8     // rows per warp

typedef unsigned long long u64;

__device__ __forceinline__ u64 pack2(float lo, float hi) {
    u64 r; asm("mov.b64 %0, {%1, %2};" : "=l"(r) : "f"(lo), "f"(hi)); return r;
}
__device__ __forceinline__ float2 unpack2(u64 v) {
    float2 f; asm("mov.b64 {%0, %1}, %2;" : "=f"(f.x), "=f"(f.y) : "l"(v)); return f;
}
__device__ __forceinline__ u64 fma2(u64 a, u64 b, u64 c) {
    u64 d;
    asm("fma.rn.f32x2 %0, %1, %2, %3;" : "=l"(d) : "l"(a), "l"(b), "l"(c));
    return d;
}
// z' is PRE-SCALED by 2*log2e: tanh = 1 - 2/(1 + 2^(z'))
__device__ __forceinline__ float tanh_scaled(float zp) {
    float e, r;
    asm("ex2.approx.f32 %0, %1;" : "=f"(e) : "f"(zp));
    asm("rcp.approx.f32 %0, %1;" : "=f"(r) : "f"(e + 1.0f));
    return fmaf(-2.0f, r, 1.0f);
}

__global__ __launch_bounds__(32)
void rnn_fused_kernel(const float* __restrict__ x,
                      const float* __restrict__ Wih,
                      const float* __restrict__ Whh,
                      const float* __restrict__ bih,
                      const float* __restrict__ bhh,
                      const float* __restrict__ fcw,
                      const float* __restrict__ fcb,
                      float* __restrict__ out) {
    const float S = 2.8853900817779268f;   // 2*log2(e)

    const int lane = (int)(threadIdx.x & 31u);
    const int p    = lane & 3;              // part: units 5p..5p+4
    const int grp  = lane >> 2;             // row within warp (0..7)
    const unsigned gbase = (unsigned)(lane & ~3);
    const unsigned FULL  = 0xFFFFFFFFu;

    const int row = blockIdx.x * RPW + grp;

    // precomputed shfl source lanes for d = 1..3 (rotation)
    const unsigned sl1 = gbase + (unsigned)((p + 1) & 3);
    const unsigned sl2 = gbase + (unsigned)((p + 2) & 3);
    const unsigned sl3 = gbase + (unsigned)((p + 3) & 3);

    // ---- per-lane constants (all pre-scaled by S) ----
    // For source-rotation d, columns come from lane q=(p+d)&3: k = 5q..5q+4
    // pairs (5q,5q+1),(5q+2,5q+3) + scalar 5q+4.
    u64   W2r[UPL][4][2];   // 40 u64 = 80 regs
    float Wsr[UPL][4];      // 20 regs
    u64   w01[UPL];         // 10 regs
    float b[UPL];           // 5 regs
#pragma unroll
    for (int u = 0; u < UPL; ++u) {
        const int j = p * UPL + u;
        b[u]   = S * (bih[j] + bhh[j]);
        w01[u] = pack2(S * Wih[2 * j], S * Wih[2 * j + 1]);
#pragma unroll
        for (int d = 0; d < 4; ++d) {
            const int q = (p + d) & 3;
            const float* wr = Whh + j * HH + 5 * q;
            W2r[u][d][0] = pack2(S * wr[0], S * wr[1]);
            W2r[u][d][1] = pack2(S * wr[2], S * wr[3]);
            Wsr[u][d]    = S * wr[4];
        }
    }

    // own h state: 2 packed pairs + 1 scalar (units 5p..5p+4), init 0
    u64 pA = 0ull, pB = 0ull;
    float hS = 0.0f;
    float h[UPL];
#pragma unroll
    for (int u = 0; u < UPL; ++u) h[u] = 0.0f;

    // x: [B, T, 2]; each lane loads its OWN row (4 lanes same 16B sectors)
    const ulonglong2* xr2 =
        reinterpret_cast<const ulonglong2*>(x) + (size_t)row * (TT / 2);
    ulonglong2 xa = xr2[0];
    ulonglong2 xb = xr2[1];
    const int NC = TT / 4;    // 512 chunks of 4 steps

    for (int c = 0; c < NC; ++c) {
        const int cn = (c + 1 < NC) ? (c + 1) : 0;   // branch-free prefetch
        const ulonglong2 xna = xr2[2 * cn];
        const ulonglong2 xnb = xr2[2 * cn + 1];
        u64 xs[4] = { xa.x, xa.y, xb.x, xb.y };

#pragma unroll
        for (int s = 0; s < 4; ++s) {
            // ---- exchange: own (regs) + 3 rotated sources (15 SHFL) ----
            u64 rA[4], rB[4];
            float rS[4];
            rA[0] = pA;  rB[0] = pB;  rS[0] = hS;
            rA[1] = __shfl_sync(FULL, pA, sl1);
            rB[1] = __shfl_sync(FULL, pB, sl1);
            rS[1] = __shfl_sync(FULL, hS, sl1);
            rA[2] = __shfl_sync(FULL, pA, sl2);
            rB[2] = __shfl_sync(FULL, pB, sl2);
            rS[2] = __shfl_sync(FULL, hS, sl2);
            rA[3] = __shfl_sync(FULL, pA, sl3);
            rB[3] = __shfl_sync(FULL, pB, sl3);
            rS[3] = __shfl_sync(FULL, hS, sl3);

            // ---- MAC: 5 units, each 8 fma2-pairs + 4 scalar FFMA ----
            u64 accP[UPL];
            float accS[UPL];
#pragma unroll
            for (int u = 0; u < UPL; ++u) {
                accP[u] = fma2(xs[s], w01[u], 0ull);
                accS[u] = b[u];
            }
#pragma unroll
            for (int d = 0; d < 4; ++d) {
#pragma unroll
                for (int u = 0; u < UPL; ++u) {
                    accP[u] = fma2(rA[d], W2r[u][d][0], accP[u]);
                    accP[u] = fma2(rB[d], W2r[u][d][1], accP[u]);
                    accS[u] = fmaf(rS[d], Wsr[u][d], accS[u]);
                }
            }

            // ---- activation (pre-scaled domain) ----
#pragma unroll
            for (int u = 0; u < UPL; ++u) {
                const float2 f = unpack2(accP[u]);
                h[u] = tanh_scaled((f.x + f.y) + accS[u]);
            }
            pA = pack2(h[0], h[1]);
            pB = pack2(h[2], h[3]);
            hS = h[4];
        }
        xa = xna;
        xb = xnb;
    }

    // ---- epilogue: h_state then fc head ----
    float* hs = out + BB;   // h_state [1, B, H] right after out [B, 1]
#pragma unroll
    for (int u = 0; u < UPL; ++u)
        hs[(size_t)row * HH + p * UPL + u] = h[u];

    float ps = 0.0f;
#pragma unroll
    for (int u = 0; u < UPL; ++u)
        ps = fmaf(h[u], fcw[p * UPL + u], ps);
    ps += __shfl_xor_sync(FULL, ps, 1);
    ps += __shfl_xor_sync(FULL, ps, 2);
    if (p == 0) out[row] = ps + fcb[0];
}

extern "C" void kernel_launch(void* const* d_in, const int* in_sizes, int n_in,
                              void* d_out, int out_size) {
    const float* x   = (const float*)d_in[0];
    const float* Wih = (const float*)d_in[1];
    const float* Whh = (const float*)d_in[2];
    const float* bih = (const float*)d_in[3];
    const float* bhh = (const float*)d_in[4];
    const float* fcw = (const float*)d_in[5];
    const float* fcb = (const float*)d_in[6];
    float* out = (float*)d_out;

    rnn_fused_kernel<<<BB / RPW, 32>>>(x, Wih, Whh, bih, bhh, fcw, fcb, out);
}